// round 15
// baseline (speedup 1.0000x reference)
#include <cuda_runtime.h>
#include <cuda_bf16.h>
#include <cuda_fp16.h>
#include <cstdint>
#include <cstddef>

#define MAXN 30000
typedef unsigned long long u64;

__device__ float g_K[(size_t)MAXN * 256];
__device__ float g_SP[(size_t)MAXN * 512];
__device__ __half g_V[(size_t)MAXN * 256];
__device__ __half g_U[(size_t)MAXN * 8 * 256];
__device__ __half g_A[(size_t)MAXN * 8 * 256];
__device__ uint4 g_MH[(size_t)MAXN * 16 * 32];   // packed fp16 msg: [n][slot16][lane]
__device__ __nv_bfloat16 g_Wkh[256 * 256], g_Wkl[256 * 256];
__device__ __nv_bfloat16 g_WqTh[256 * 256], g_WqTl[256 * 256];
__device__ __half g_WspH[512 * 256];
__device__ __half g_WfinH[256 * 256];
__device__ __half g_WvH[256 * 256];
__device__ int g_maskMode;

// streams + events, created once at load time (host objects only)
static cudaStream_t g_s1, g_s2;
static cudaEvent_t g_evFork, g_evPrep, g_evS1, g_evS2;
namespace {
struct StreamInit {
    StreamInit() {
        cudaStreamCreateWithFlags(&g_s1, cudaStreamNonBlocking);
        cudaStreamCreateWithFlags(&g_s2, cudaStreamNonBlocking);
        cudaEventCreateWithFlags(&g_evFork, cudaEventDisableTiming);
        cudaEventCreateWithFlags(&g_evPrep, cudaEventDisableTiming);
        cudaEventCreateWithFlags(&g_evS1, cudaEventDisableTiming);
        cudaEventCreateWithFlags(&g_evS2, cudaEventDisableTiming);
    }
};
StreamInit g_streamInit;
}

// packed fp32x2 ops (Blackwell; full fp32 precision, 2x issue rate)
#define PACK2(o, lo, hi) asm("mov.b64 %0, {%1,%2};" : "=l"(o) : "f"(lo), "f"(hi))
#define UNPACK2(lo, hi, v) asm("mov.b64 {%0,%1}, %2;" : "=f"(lo), "=f"(hi) : "l"(v))
#define FMA2(d, a, b, c) asm("fma.rn.f32x2 %0, %1, %2, %3;" : "=l"(d) : "l"(a), "l"(b), "l"(c))
#define MUL2(d, a, b) asm("mul.rn.f32x2 %0, %1, %2;" : "=l"(d) : "l"(a), "l"(b))

// ---------------- mask dtype detection (deterministic) ----------------
__global__ void detect_kernel(const unsigned char* __restrict__ m, int nelem) {
    __shared__ int s_nzoff, s_badf, s_anyf;
    if (threadIdx.x == 0) { s_nzoff = 0; s_badf = 0; s_anyf = 0; }
    __syncthreads();
    int words = min(nelem / 4, 1024);
    const unsigned int* wm = (const unsigned int*)m;
    int nz = 0, bf = 0, af = 0;
    for (int i = threadIdx.x; i < words; i += blockDim.x) {
        unsigned int w = wm[i];
        if (w >> 8) nz = 1;
        if (w != 0u && w != 0x3F800000u) bf = 1;
        if (w == 0x3F800000u) af = 1;
    }
    if (nz) atomicOr(&s_nzoff, 1);
    if (bf) atomicOr(&s_badf, 1);
    if (af) atomicOr(&s_anyf, 1);
    __syncthreads();
    if (threadIdx.x == 0)
        g_maskMode = (!s_badf && s_anyf) ? 2 : (!s_nzoff ? 1 : 0);
}

__device__ __forceinline__ bool mask_at(const void* p, int i, int mode) {
    if (mode == 0) return ((const unsigned char*)p)[i] != 0;
    if (mode == 1) return ((const int*)p)[i] != 0;
    return ((const float*)p)[i] != 0.0f;
}

// ---------------- msg fp16 pack: warp handles one (n, slot) -----------------
__global__ __launch_bounds__(256) void cvt_msg(const float* __restrict__ src,
                                               int slotBase, int total) {
    const int idx = blockIdx.x * 8 + (threadIdx.x >> 5);
    if (idx >= total) return;
    const int lane = threadIdx.x & 31;
    const int n = idx >> 3, s = idx & 7;
    const float* p = src + (size_t)n * 2048 + (size_t)s * 256;
    float m[8];
#pragma unroll
    for (int j = 0; j < 8; j++) m[j] = p[j * 32 + lane];
    uint32_t w[4];
#pragma unroll
    for (int j = 0; j < 4; j++) {
        __half2 h = __floats2half2_rn(m[j], m[j + 4]);
        w[j] = *(uint32_t*)&h;
    }
    g_MH[((size_t)n * 16 + slotBase + s) * 32 + lane] = make_uint4(w[0], w[1], w[2], w[3]);
}

// ---------------- weight prep: one kernel, 6 jobs ----------------
__global__ void prep_weights(const float* __restrict__ Wself, const float* __restrict__ Wpar,
                             const float* __restrict__ Wfin, const float* __restrict__ Wv,
                             const float* __restrict__ Wk, const float* __restrict__ Wq) {
    int r = blockIdx.x * 4 + (threadIdx.x >> 8);
    int c = threadIdx.x & 255;
    int job = blockIdx.y;
    size_t idx = (size_t)r * 256 + c;
    switch (job) {
        case 0: g_WspH[idx] = __float2half_rn(Wself[idx]); break;
        case 1: g_WspH[idx + 256 * 256] = __float2half_rn(Wpar[idx]); break;
        case 2: g_WfinH[idx] = __float2half_rn(Wfin[idx]); break;
        case 3: g_WvH[idx] = __float2half_rn(Wv[idx]); break;
        case 4: {
            float x = Wk[idx];
            __nv_bfloat16 h = __float2bfloat16(x);
            g_Wkh[idx] = h;
            g_Wkl[idx] = __float2bfloat16(x - __bfloat162float(h));
            break;
        }
        case 5: {
            float x = Wq[(size_t)c * 256 + r];  // transpose
            __nv_bfloat16 h = __float2bfloat16(x);
            g_WqTh[idx] = h;
            g_WqTl[idx] = __float2bfloat16(x - __bfloat162float(h));
            break;
        }
    }
}

// ---------------- helpers ----------------
__device__ __forceinline__ void split8(float4 a, float4 b, uint4& h, uint4& l) {
    float x[8] = {a.x, a.y, a.z, a.w, b.x, b.y, b.z, b.w};
    uint32_t hw[4], lw[4];
#pragma unroll
    for (int p = 0; p < 4; p++) {
        __nv_bfloat16 h0 = __float2bfloat16(x[2 * p]);
        __nv_bfloat16 h1 = __float2bfloat16(x[2 * p + 1]);
        __nv_bfloat16 l0 = __float2bfloat16(x[2 * p] - __bfloat162float(h0));
        __nv_bfloat16 l1 = __float2bfloat16(x[2 * p + 1] - __bfloat162float(h1));
        hw[p] = ((uint32_t)__bfloat16_as_ushort(h1) << 16) | __bfloat16_as_ushort(h0);
        lw[p] = ((uint32_t)__bfloat16_as_ushort(l1) << 16) | __bfloat16_as_ushort(l0);
    }
    h = make_uint4(hw[0], hw[1], hw[2], hw[3]);
    l = make_uint4(lw[0], lw[1], lw[2], lw[3]);
}

__device__ __forceinline__ uint4 cvt8_f16(float4 a, float4 b) {
    uint32_t w[4];
    w[0] = ((uint32_t)__half_as_ushort(__float2half_rn(a.y)) << 16) | __half_as_ushort(__float2half_rn(a.x));
    w[1] = ((uint32_t)__half_as_ushort(__float2half_rn(a.w)) << 16) | __half_as_ushort(__float2half_rn(a.z));
    w[2] = ((uint32_t)__half_as_ushort(__float2half_rn(b.y)) << 16) | __half_as_ushort(__float2half_rn(b.x));
    w[3] = ((uint32_t)__half_as_ushort(__float2half_rn(b.w)) << 16) | __half_as_ushort(__float2half_rn(b.z));
    return make_uint4(w[0], w[1], w[2], w[3]);
}

#define MMA_BF16(d, a, b) asm volatile( \
    "mma.sync.aligned.m16n8k16.row.col.f32.bf16.bf16.f32 " \
    "{%0,%1,%2,%3}, {%4,%5,%6,%7}, {%8,%9}, {%0,%1,%2,%3};\n" \
    : "+f"(d[0]), "+f"(d[1]), "+f"(d[2]), "+f"(d[3]) \
    : "r"(a[0]), "r"(a[1]), "r"(a[2]), "r"(a[3]), "r"(b[0]), "r"(b[1]))

#define MMA_F16(d, a, b) asm volatile( \
    "mma.sync.aligned.m16n8k16.row.col.f32.f16.f16.f32 " \
    "{%0,%1,%2,%3}, {%4,%5,%6,%7}, {%8,%9}, {%0,%1,%2,%3};\n" \
    : "+f"(d[0]), "+f"(d[1]), "+f"(d[2]), "+f"(d[3]) \
    : "r"(a[0]), "r"(a[1]), "r"(a[2]), "r"(a[3]), "r"(b[0]), "r"(b[1]))

// ---------------- 3-split bf16 GEMM (score path) ----------------
__global__ __launch_bounds__(256) void gemm_f32s(
    const float* __restrict__ A, long lda,
    const __nv_bfloat16* __restrict__ Bh, const __nv_bfloat16* __restrict__ Bl,
    float* __restrict__ C, int M) {
    __shared__ __nv_bfloat16 sAh[128][40], sAl[128][40];
    __shared__ __nv_bfloat16 sBh[64][40], sBl[64][40];
    const int t = threadIdx.x, lane = t & 31, w = t >> 5;
    const int m0 = blockIdx.x * 128, n0 = blockIdx.y * 64;
    const int wr = (w & 3) * 32, wc = (w >> 2) * 32;
    float acc[2][4][4];
#pragma unroll
    for (int i = 0; i < 2; i++)
#pragma unroll
        for (int j = 0; j < 4; j++)
#pragma unroll
            for (int q = 0; q < 4; q++) acc[i][j][q] = 0.f;

    const int ar = t >> 1, ao = (t & 1) * 16;
    const int br = t >> 2, bo = (t & 3) * 8;
    const int am = m0 + ar;
    const bool aok = (am < M);
    const float* pA = A + (size_t)(aok ? am : 0) * lda + ao;
    const __nv_bfloat16* pBh = Bh + (size_t)(n0 + br) * 256 + bo;
    const __nv_bfloat16* pBl = Bl + (size_t)(n0 + br) * 256 + bo;

    for (int k0 = 0; k0 < 256; k0 += 32) {
        float4 z = make_float4(0, 0, 0, 0);
        float4 a0 = aok ? *(const float4*)(pA + k0)      : z;
        float4 a1 = aok ? *(const float4*)(pA + k0 + 4)  : z;
        float4 a2 = aok ? *(const float4*)(pA + k0 + 8)  : z;
        float4 a3 = aok ? *(const float4*)(pA + k0 + 12) : z;
        uint4 h0, l0, h1, l1;
        split8(a0, a1, h0, l0);
        split8(a2, a3, h1, l1);
        *(uint4*)&sAh[ar][ao]     = h0;
        *(uint4*)&sAh[ar][ao + 8] = h1;
        *(uint4*)&sAl[ar][ao]     = l0;
        *(uint4*)&sAl[ar][ao + 8] = l1;
        *(uint4*)&sBh[br][bo] = *(const uint4*)(pBh + k0);
        *(uint4*)&sBl[br][bo] = *(const uint4*)(pBl + k0);
        __syncthreads();
#pragma unroll
        for (int kk = 0; kk < 32; kk += 16) {
            uint32_t afh[2][4], afl[2][4], bfh[4][2], bfl[4][2];
            const int arow = wr + (lane >> 2);
            const int acol = kk + (lane & 3) * 2;
#pragma unroll
            for (int mt = 0; mt < 2; mt++) {
                const int r0 = arow + mt * 16;
                afh[mt][0] = *(const uint32_t*)&sAh[r0][acol];
                afh[mt][1] = *(const uint32_t*)&sAh[r0 + 8][acol];
                afh[mt][2] = *(const uint32_t*)&sAh[r0][acol + 8];
                afh[mt][3] = *(const uint32_t*)&sAh[r0 + 8][acol + 8];
                afl[mt][0] = *(const uint32_t*)&sAl[r0][acol];
                afl[mt][1] = *(const uint32_t*)&sAl[r0 + 8][acol];
                afl[mt][2] = *(const uint32_t*)&sAl[r0][acol + 8];
                afl[mt][3] = *(const uint32_t*)&sAl[r0 + 8][acol + 8];
            }
#pragma unroll
            for (int nt = 0; nt < 4; nt++) {
                const int nr = wc + nt * 8 + (lane >> 2);
                bfh[nt][0] = *(const uint32_t*)&sBh[nr][acol];
                bfh[nt][1] = *(const uint32_t*)&sBh[nr][acol + 8];
                bfl[nt][0] = *(const uint32_t*)&sBl[nr][acol];
                bfl[nt][1] = *(const uint32_t*)&sBl[nr][acol + 8];
            }
#pragma unroll
            for (int mt = 0; mt < 2; mt++)
#pragma unroll
                for (int nt = 0; nt < 4; nt++) {
                    MMA_BF16(acc[mt][nt], afh[mt], bfh[nt]);
                    MMA_BF16(acc[mt][nt], afh[mt], bfl[nt]);
                    MMA_BF16(acc[mt][nt], afl[mt], bfh[nt]);
                }
        }
        __syncthreads();
    }
    const int grp = lane >> 2, qc = (lane & 3) * 2;
#pragma unroll
    for (int mt = 0; mt < 2; mt++)
#pragma unroll
        for (int nt = 0; nt < 4; nt++) {
            const int rg = m0 + wr + mt * 16 + grp;
            const int cg = n0 + wc + nt * 8 + qc;
            if (rg < M)
                *(float2*)&C[(size_t)rg * 256 + cg] =
                    make_float2(acc[mt][nt][0], acc[mt][nt][1]);
            if (rg + 8 < M)
                *(float2*)&C[(size_t)(rg + 8) * 256 + cg] =
                    make_float2(acc[mt][nt][2], acc[mt][nt][3]);
        }
}

// ---------------- fp16 GEMM, A fp32 in gmem (prefetch kept) ----------------
__global__ __launch_bounds__(256) void gemm_f16(
    const float* __restrict__ A, long lda,
    const __half* __restrict__ B,
    float* __restrict__ C, long ldc, int M) {
    __shared__ __half sA[128][40];
    __shared__ __half sB[64][40];
    const int t = threadIdx.x, lane = t & 31, w = t >> 5;
    const int m0 = blockIdx.x * 128, n0 = blockIdx.y * 64;
    const int wr = (w & 3) * 32, wc = (w >> 2) * 32;
    float acc[2][4][4];
#pragma unroll
    for (int i = 0; i < 2; i++)
#pragma unroll
        for (int j = 0; j < 4; j++)
#pragma unroll
            for (int q = 0; q < 4; q++) acc[i][j][q] = 0.f;

    const int ar = t >> 1, ao = (t & 1) * 16;
    const int br = t >> 2, bo = (t & 3) * 8;
    const int am = m0 + ar;
    const bool aok = (am < M);
    const float* pA = A + (size_t)(aok ? am : 0) * lda + ao;
    const __half* pB = B + (size_t)(n0 + br) * 256 + bo;

    const float4 z = make_float4(0, 0, 0, 0);
    float4 a0 = aok ? *(const float4*)(pA)      : z;
    float4 a1 = aok ? *(const float4*)(pA + 4)  : z;
    float4 a2 = aok ? *(const float4*)(pA + 8)  : z;
    float4 a3 = aok ? *(const float4*)(pA + 12) : z;
    uint4 rb = *(const uint4*)(pB);

    for (int k0 = 0; k0 < 256; k0 += 32) {
        *(uint4*)&sA[ar][ao]     = cvt8_f16(a0, a1);
        *(uint4*)&sA[ar][ao + 8] = cvt8_f16(a2, a3);
        *(uint4*)&sB[br][bo] = rb;
        __syncthreads();
        if (k0 + 32 < 256) {
            const int kn = k0 + 32;
            a0 = aok ? *(const float4*)(pA + kn)      : z;
            a1 = aok ? *(const float4*)(pA + kn + 4)  : z;
            a2 = aok ? *(const float4*)(pA + kn + 8)  : z;
            a3 = aok ? *(const float4*)(pA + kn + 12) : z;
            rb = *(const uint4*)(pB + kn);
        }
#pragma unroll
        for (int kk = 0; kk < 32; kk += 16) {
            uint32_t af[2][4], bf[4][2];
            const int arow = wr + (lane >> 2);
            const int acol = kk + (lane & 3) * 2;
#pragma unroll
            for (int mt = 0; mt < 2; mt++) {
                const int r0 = arow + mt * 16;
                af[mt][0] = *(const uint32_t*)&sA[r0][acol];
                af[mt][1] = *(const uint32_t*)&sA[r0 + 8][acol];
                af[mt][2] = *(const uint32_t*)&sA[r0][acol + 8];
                af[mt][3] = *(const uint32_t*)&sA[r0 + 8][acol + 8];
            }
#pragma unroll
            for (int nt = 0; nt < 4; nt++) {
                const int nr = wc + nt * 8 + (lane >> 2);
                bf[nt][0] = *(const uint32_t*)&sB[nr][acol];
                bf[nt][1] = *(const uint32_t*)&sB[nr][acol + 8];
            }
#pragma unroll
            for (int mt = 0; mt < 2; mt++)
#pragma unroll
                for (int nt = 0; nt < 4; nt++)
                    MMA_F16(acc[mt][nt], af[mt], bf[nt]);
        }
        __syncthreads();
    }
    const int grp = lane >> 2, qc = (lane & 3) * 2;
#pragma unroll
    for (int mt = 0; mt < 2; mt++)
#pragma unroll
        for (int nt = 0; nt < 4; nt++) {
            const int rg = m0 + wr + mt * 16 + grp;
            const int cg = n0 + wc + nt * 8 + qc;
            if (rg < M)
                *(float2*)&C[(size_t)rg * ldc + cg] =
                    make_float2(acc[mt][nt][0], acc[mt][nt][1]);
            if (rg + 8 < M)
                *(float2*)&C[(size_t)(rg + 8) * ldc + cg] =
                    make_float2(acc[mt][nt][2], acc[mt][nt][3]);
        }
}

// ---------------- fp16 GEMM, A fp16 in gmem (final proj) -------------------
__global__ __launch_bounds__(256) void gemm_h16(
    const __half* __restrict__ A,
    const __half* __restrict__ B,
    float* __restrict__ C, int M) {
    __shared__ __half sA[128][40];
    __shared__ __half sB[64][40];
    const int t = threadIdx.x, lane = t & 31, w = t >> 5;
    const int m0 = blockIdx.x * 128, n0 = blockIdx.y * 64;
    const int wr = (w & 3) * 32, wc = (w >> 2) * 32;
    float acc[2][4][4];
#pragma unroll
    for (int i = 0; i < 2; i++)
#pragma unroll
        for (int j = 0; j < 4; j++)
#pragma unroll
            for (int q = 0; q < 4; q++) acc[i][j][q] = 0.f;

    const int ar = t >> 1, ao = (t & 1) * 16;
    const int br = t >> 2, bo = (t & 3) * 8;
    const int am = m0 + ar;
    const bool aok = (am < M);
    const __half* pA = A + (size_t)(aok ? am : 0) * 256 + ao;
    const __half* pB = B + (size_t)(n0 + br) * 256 + bo;

    const uint4 uz = make_uint4(0, 0, 0, 0);
    uint4 ra0 = aok ? *(const uint4*)(pA)     : uz;
    uint4 ra1 = aok ? *(const uint4*)(pA + 8) : uz;
    uint4 rb  = *(const uint4*)(pB);

    for (int k0 = 0; k0 < 256; k0 += 32) {
        *(uint4*)&sA[ar][ao]     = ra0;
        *(uint4*)&sA[ar][ao + 8] = ra1;
        *(uint4*)&sB[br][bo] = rb;
        __syncthreads();
        if (k0 + 32 < 256) {
            const int kn = k0 + 32;
            ra0 = aok ? *(const uint4*)(pA + kn)     : uz;
            ra1 = aok ? *(const uint4*)(pA + kn + 8) : uz;
            rb  = *(const uint4*)(pB + kn);
        }
#pragma unroll
        for (int kk = 0; kk < 32; kk += 16) {
            uint32_t af[2][4], bf[4][2];
            const int arow = wr + (lane >> 2);
            const int acol = kk + (lane & 3) * 2;
#pragma unroll
            for (int mt = 0; mt < 2; mt++) {
                const int r0 = arow + mt * 16;
                af[mt][0] = *(const uint32_t*)&sA[r0][acol];
                af[mt][1] = *(const uint32_t*)&sA[r0 + 8][acol];
                af[mt][2] = *(const uint32_t*)&sA[r0][acol + 8];
                af[mt][3] = *(const uint32_t*)&sA[r0 + 8][acol + 8];
            }
#pragma unroll
            for (int nt = 0; nt < 4; nt++) {
                const int nr = wc + nt * 8 + (lane >> 2);
                bf[nt][0] = *(const uint32_t*)&sB[nr][acol];
                bf[nt][1] = *(const uint32_t*)&sB[nr][acol + 8];
            }
#pragma unroll
            for (int mt = 0; mt < 2; mt++)
#pragma unroll
                for (int nt = 0; nt < 4; nt++)
                    MMA_F16(acc[mt][nt], af[mt], bf[nt]);
        }
        __syncthreads();
    }
    const int grp = lane >> 2, qc = (lane & 3) * 2;
#pragma unroll
    for (int mt = 0; mt < 2; mt++)
#pragma unroll
        for (int nt = 0; nt < 4; nt++) {
            const int rg = m0 + wr + mt * 16 + grp;
            const int cg = n0 + wc + nt * 8 + qc;
            if (rg < M)
                *(float2*)&C[(size_t)rg * 256 + cg] =
                    make_float2(acc[mt][nt][0], acc[mt][nt][1]);
            if (rg + 8 < M)
                *(float2*)&C[(size_t)(rg + 8) * 256 + cg] =
                    make_float2(acc[mt][nt][2], acc[mt][nt][3]);
        }
}

// ---------------- u via tensor cores: A staged once, i0 loop inside ---------
__global__ __launch_bounds__(256) void u_tc(int M) {
    __shared__ __nv_bfloat16 sAh[128][40], sAl[128][40];
    __shared__ __nv_bfloat16 sBh[64][40], sBl[64][40];
    const int t = threadIdx.x, lane = t & 31, w = t >> 5;
    const int m0 = blockIdx.x * 128, h = blockIdx.y;
    const int wr = (w & 3) * 32, wc = (w >> 2) * 32;
    const int ar = t >> 1, ao = (t & 1) * 16;
    const int br = t >> 2, bo = (t & 3) * 8;
    const int am = m0 + ar;
    const bool aok = (am < M);
    const int grp = lane >> 2, qc = (lane & 3) * 2;

    {
        float4 z = make_float4(0, 0, 0, 0);
        const float* pA = g_K + (size_t)(aok ? am : 0) * 256 + h * 32 + ao;
        float4 a0 = aok ? *(const float4*)(pA)      : z;
        float4 a1 = aok ? *(const float4*)(pA + 4)  : z;
        float4 a2 = aok ? *(const float4*)(pA + 8)  : z;
        float4 a3 = aok ? *(const float4*)(pA + 12) : z;
        uint4 h0, l0, h1, l1;
        split8(a0, a1, h0, l0);
        split8(a2, a3, h1, l1);
        *(uint4*)&sAh[ar][ao]     = h0;
        *(uint4*)&sAh[ar][ao + 8] = h1;
        *(uint4*)&sAl[ar][ao]     = l0;
        *(uint4*)&sAl[ar][ao + 8] = l1;
    }

    for (int i0 = 0; i0 < 256; i0 += 64) {
        __syncthreads();
        *(uint4*)&sBh[br][bo] = *(const uint4*)&g_WqTh[(size_t)(i0 + br) * 256 + h * 32 + bo];
        *(uint4*)&sBl[br][bo] = *(const uint4*)&g_WqTl[(size_t)(i0 + br) * 256 + h * 32 + bo];
        __syncthreads();

        float acc[2][4][4];
#pragma unroll
        for (int i = 0; i < 2; i++)
#pragma unroll
            for (int j = 0; j < 4; j++)
#pragma unroll
                for (int q = 0; q < 4; q++) acc[i][j][q] = 0.f;

#pragma unroll
        for (int kk = 0; kk < 32; kk += 16) {
            uint32_t afh[2][4], afl[2][4], bfh[4][2], bfl[4][2];
            const int arow = wr + (lane >> 2);
            const int acol = kk + (lane & 3) * 2;
#pragma unroll
            for (int mt = 0; mt < 2; mt++) {
                const int r0 = arow + mt * 16;
                afh[mt][0] = *(const uint32_t*)&sAh[r0][acol];
                afh[mt][1] = *(const uint32_t*)&sAh[r0 + 8][acol];
                afh[mt][2] = *(const uint32_t*)&sAh[r0][acol + 8];
                afh[mt][3] = *(const uint32_t*)&sAh[r0 + 8][acol + 8];
                afl[mt][0] = *(const uint32_t*)&sAl[r0][acol];
                afl[mt][1] = *(const uint32_t*)&sAl[r0 + 8][acol];
                afl[mt][2] = *(const uint32_t*)&sAl[r0][acol + 8];
                afl[mt][3] = *(const uint32_t*)&sAl[r0 + 8][acol + 8];
            }
#pragma unroll
            for (int nt = 0; nt < 4; nt++) {
                const int nr = wc + nt * 8 + (lane >> 2);
                bfh[nt][0] = *(const uint32_t*)&sBh[nr][acol];
                bfh[nt][1] = *(const uint32_t*)&sBh[nr][acol + 8];
                bfl[nt][0] = *(const uint32_t*)&sBl[nr][acol];
                bfl[nt][1] = *(const uint32_t*)&sBl[nr][acol + 8];
            }
#pragma unroll
            for (int mt = 0; mt < 2; mt++)
#pragma unroll
                for (int nt = 0; nt < 4; nt++) {
                    MMA_BF16(acc[mt][nt], afh[mt], bfh[nt]);
                    MMA_BF16(acc[mt][nt], afh[mt], bfl[nt]);
                    MMA_BF16(acc[mt][nt], afl[mt], bfh[nt]);
                }
        }

#pragma unroll
        for (int mt = 0; mt < 2; mt++)
#pragma unroll
            for (int nt = 0; nt < 4; nt++) {
                const int rg = m0 + wr + mt * 16 + grp;
                const int cg = h * 256 + i0 + wc + nt * 8 + qc;
                if (rg < M) {
                    __half2 v = __floats2half2_rn(acc[mt][nt][0], acc[mt][nt][1]);
                    *(__half2*)&g_U[(size_t)rg * 2048 + cg] = v;
                }
                if (rg + 8 < M) {
                    __half2 v = __floats2half2_rn(acc[mt][nt][2], acc[mt][nt][3]);
                    *(__half2*)&g_U[(size_t)(rg + 8) * 2048 + cg] = v;
                }
            }
    }
}

// ---------------- vproj: A fp16 in gmem, fp16 Wv, fp16 V out ---------------
__global__ __launch_bounds__(256) void vproj_f16(int M) {
    __shared__ __half sA[128][40];
    __shared__ __half sB[32][40];
    const int t = threadIdx.x, lane = t & 31, w = t >> 5;
    const int m0 = blockIdx.x * 128, h = blockIdx.y;
    const int wr = (w & 3) * 32, wc = (w >> 2) * 16;
    float acc[2][2][4];
#pragma unroll
    for (int i = 0; i < 2; i++)
#pragma unroll
        for (int j = 0; j < 2; j++)
#pragma unroll
            for (int q = 0; q < 4; q++) acc[i][j][q] = 0.f;

    const int ar = t >> 1, ao = (t & 1) * 16;
    const int br = t >> 3, bo = (t & 7) * 4;
    const int am = m0 + ar;
    const bool aok = (am < M);
    const __half* pA = g_A + (size_t)(aok ? am : 0) * 2048 + h * 256 + ao;
    const __half* pB = g_WvH + (size_t)(h * 32 + br) * 256 + bo;

    const uint4 uz = make_uint4(0, 0, 0, 0);
    uint4 ra0 = aok ? *(const uint4*)(pA)     : uz;
    uint4 ra1 = aok ? *(const uint4*)(pA + 8) : uz;
    uint2 rb  = *(const uint2*)(pB);

    for (int k0 = 0; k0 < 256; k0 += 32) {
        *(uint4*)&sA[ar][ao]     = ra0;
        *(uint4*)&sA[ar][ao + 8] = ra1;
        *(uint2*)&sB[br][bo] = rb;
        __syncthreads();
        if (k0 + 32 < 256) {
            const int kn = k0 + 32;
            ra0 = aok ? *(const uint4*)(pA + kn)     : uz;
            ra1 = aok ? *(const uint4*)(pA + kn + 8) : uz;
            rb  = *(const uint2*)(pB + kn);
        }
#pragma unroll
        for (int kk = 0; kk < 32; kk += 16) {
            uint32_t af[2][4], bf[2][2];
            const int arow = wr + (lane >> 2);
            const int acol = kk + (lane & 3) * 2;
#pragma unroll
            for (int mt = 0; mt < 2; mt++) {
                const int r0 = arow + mt * 16;
                af[mt][0] = *(const uint32_t*)&sA[r0][acol];
                af[mt][1] = *(const uint32_t*)&sA[r0 + 8][acol];
                af[mt][2] = *(const uint32_t*)&sA[r0][acol + 8];
                af[mt][3] = *(const uint32_t*)&sA[r0 + 8][acol + 8];
            }
#pragma unroll
            for (int nt = 0; nt < 2; nt++) {
                const int nr = wc + nt * 8 + (lane >> 2);
                bf[nt][0] = *(const uint32_t*)&sB[nr][acol];
                bf[nt][1] = *(const uint32_t*)&sB[nr][acol + 8];
            }
#pragma unroll
            for (int mt = 0; mt < 2; mt++)
#pragma unroll
                for (int nt = 0; nt < 2; nt++)
                    MMA_F16(acc[mt][nt], af[mt], bf[nt]);
        }
        __syncthreads();
    }
    const int grp = lane >> 2, qc = (lane & 3) * 2;
#pragma unroll
    for (int mt = 0; mt < 2; mt++)
#pragma unroll
        for (int nt = 0; nt < 2; nt++) {
            const int rg = m0 + wr + mt * 16 + grp;
            const int cg = h * 32 + wc + nt * 8 + qc;
            if (rg < M) {
                __half2 v = __floats2half2_rn(acc[mt][nt][0], acc[mt][nt][1]);
                *(__half2*)&g_V[(size_t)rg * 256 + cg] = v;
            }
            if (rg + 8 < M) {
                __half2 v = __floats2half2_rn(acc[mt][nt][2], acc[mt][nt][3]);
                *(__half2*)&g_V[(size_t)(rg + 8) * 256 + cg] = v;
            }
        }
}

// ---------------- attention: warp-per-node, fp16 packed msg -----------------
__device__ __forceinline__ void load_mp(u64 mp[4], const uint4* __restrict__ mh,
                                        const float* __restrict__ sp,
                                        size_t nb, size_t ppar, int s, int lane) {
    if (s == 8 || s == 9) {
        const float* src = (s == 8) ? (sp + nb * 512) : (sp + ppar);
#pragma unroll
        for (int j = 0; j < 4; j++)
            PACK2(mp[j], src[j * 32 + lane], src[(j + 4) * 32 + lane]);
    } else {
        const int sl = (s < 8) ? s : (s - 2);
        uint4 v = mh[(nb * 16 + sl) * 32 + lane];
        uint32_t wv[4] = {v.x, v.y, v.z, v.w};
#pragma unroll
        for (int j = 0; j < 4; j++) {
            float2 f = __half22float2(*(__half2*)&wv[j]);
            PACK2(mp[j], f.x, f.y);
        }
    }
}

__global__ __launch_bounds__(128) void attn_fused(
        const void* __restrict__ ccwm, const void* __restrict__ cwm,
        const int* __restrict__ pidx, int N) {
    __shared__ float p_sm[4][8][20];
    const int t = threadIdx.x, lane = t & 31, w = t >> 5;
    const int n = blockIdx.x * 4 + w;
    if (n >= N) return;
    const size_t nb = n;
    const int mode = g_maskMode;
    const int myh = (((lane >> 4) & 1) << 2) | (((lane >> 3) & 1) << 1) | ((lane >> 2) & 1);
    const float NEG = __int_as_float(0xff800000);
    const float SCALE = 0.17677669529663688f;
    const size_t ppar = (size_t)pidx[n] * 512 + 256;

    u64 up[8][4];
#pragma unroll
    for (int h = 0; h < 8; h++)
#pragma unroll
        for (int j = 0; j < 4; j++) {
            float lo = __half2float(g_U[nb * 2048 + h * 256 + j * 32 + lane]);
            float hi = __half2float(g_U[nb * 2048 + h * 256 + (j + 4) * 32 + lane]);
            PACK2(up[h][j], lo, hi);
        }

    float sc[18];
#pragma unroll
    for (int s = 0; s < 18; s++) {
        u64 mp[4];
        load_mp(mp, g_MH, g_SP, nb, ppar, s, lane);
        float part[8];
#pragma unroll
        for (int h = 0; h < 8; h++) {
            u64 a;
            MUL2(a, mp[0], up[h][0]);
            FMA2(a, mp[1], up[h][1], a);
            FMA2(a, mp[2], up[h][2], a);
            FMA2(a, mp[3], up[h][3], a);
            float lo, hi;
            UNPACK2(lo, hi, a);
            part[h] = lo + hi;
        }
#pragma unroll
        for (int i = 0; i < 4; i++) {
            float a = part[i], b = part[i + 4];
            float send = (lane & 16) ? a : b;
            float recv = __shfl_xor_sync(0xFFFFFFFFu, send, 16);
            part[i] = ((lane & 16) ? b : a) + recv;
        }
#pragma unroll
        for (int i = 0; i < 2; i++) {
            float a = part[i], b = part[i + 2];
            float send = (lane & 8) ? a : b;
            float recv = __shfl_xor_sync(0xFFFFFFFFu, send, 8);
            part[i] = ((lane & 8) ? b : a) + recv;
        }
        {
            float a = part[0], b = part[1];
            float send = (lane & 4) ? a : b;
            float recv = __shfl_xor_sync(0xFFFFFFFFu, send, 4);
            part[0] = ((lane & 4) ? b : a) + recv;
        }
        part[0] += __shfl_xor_sync(0xFFFFFFFFu, part[0], 2);
        part[0] += __shfl_xor_sync(0xFFFFFFFFu, part[0], 1);
        sc[s] = part[0];
    }

    unsigned vb = 3u << 8;
#pragma unroll
    for (int s = 0; s < 8; s++)
        if (mask_at(ccwm, n * 8 + s, mode)) vb |= 1u << s;
#pragma unroll
    for (int s = 0; s < 8; s++)
        if (mask_at(cwm, n * 8 + s, mode)) vb |= 1u << (10 + s);
    float mx = NEG;
#pragma unroll
    for (int s = 0; s < 18; s++)
        if ((vb >> s) & 1) mx = fmaxf(mx, sc[s] * SCALE);
    float sum = 0.f;
    float pr[18];
#pragma unroll
    for (int s = 0; s < 18; s++) {
        float e = ((vb >> s) & 1) ? __expf(sc[s] * SCALE - mx) : 0.f;
        pr[s] = e;
        sum += e;
    }
    const float inv = 1.f / sum;
    if ((lane & 3) == 0) {
#pragma unroll
        for (int s = 0; s < 18; s++) p_sm[w][myh][s] = pr[s] * inv;
    }
    __syncwarp();

    u64 acc2[8][4];
#pragma unroll
    for (int h = 0; h < 8; h++)
#pragma unroll
        for (int j = 0; j < 4; j++) acc2[h][j] = 0ULL;
#pragma unroll
    for (int s = 0; s < 18; s++) {
        u64 mp[4];
        load_mp(mp, g_MH, g_SP, nb, ppar, s, lane);
#pragma unroll
        for (int h = 0; h < 8; h++) {
            float ph = p_sm[w][h][s];
            u64 pp;
            PACK2(pp, ph, ph);
#pragma unroll
            for (int j = 0; j < 4; j++)
                FMA2(acc2[h][j], pp, mp[j], acc2[h][j]);
        }
    }
#pragma unroll
    for (int h = 0; h < 8; h++)
#pragma unroll
        for (int j = 0; j < 4; j++) {
            float lo, hi;
            UNPACK2(lo, hi, acc2[h][j]);
            g_A[nb * 2048 + h * 256 + j * 32 + lane] = __float2half_rn(lo);
            g_A[nb * 2048 + h * 256 + (j + 4) * 32 + lane] = __float2half_rn(hi);
        }
}

extern "C" void kernel_launch(void* const* d_in, const int* in_sizes, int n_in,
                              void* d_out, int out_size) {
    const float* X    = (const float*)d_in[0];
    const int*   pidx = (const int*)d_in[1];
    const float* ccw  = (const float*)d_in[2];
    const void*  ccwm = d_in[3];
    const float* cw   = (const float*)d_in[4];
    const void*  cwm  = d_in[5];
    const float* Wself = (const float*)d_in[6];
    const float* Wpar  = (const float*)d_in[7];
    const float* Wq    = (const float*)d_in[8];
    const float* Wk    = (const float*)d_in[9];
    const float* Wv    = (const float*)d_in[10];
    const float* Wfin  = (const float*)d_in[11];
    float* out = (float*)d_out;
    const int N = in_sizes[0] / 256;

    float *pK, *pSP;
    __half *pV;
    __nv_bfloat16 *pWkh, *pWkl;
    __half *pWspH, *pWfinH;
    cudaGetSymbolAddress((void**)&pK, g_K);
    cudaGetSymbolAddress((void**)&pV, g_V);
    cudaGetSymbolAddress((void**)&pSP, g_SP);
    cudaGetSymbolAddress((void**)&pWkh, g_Wkh);
    cudaGetSymbolAddress((void**)&pWkl, g_Wkl);
    cudaGetSymbolAddress((void**)&pWspH, g_WspH);
    cudaGetSymbolAddress((void**)&pWfinH, g_WfinH);

    const int MB = (N + 127) / 128;
    const int CB = (N * 8 + 7) / 8;

    // fork for input-only work (cvt kernels need no weights)
    cudaEventRecord(g_evFork, 0);
    cudaStreamWaitEvent(g_s1, g_evFork, 0);
    cudaStreamWaitEvent(g_s2, g_evFork, 0);

    cvt_msg<<<CB, 256, 0, g_s2>>>(cw, 8, N * 8);
    cudaEventRecord(g_evS2, g_s2);

    cvt_msg<<<CB, 256, 0, g_s1>>>(ccw, 0, N * 8);

    detect_kernel<<<1, 256>>>((const unsigned char*)ccwm, in_sizes[3]);
    prep_weights<<<dim3(64, 6), 1024>>>(Wself, Wpar, Wfin, Wv, Wk, Wq);
    cudaEventRecord(g_evPrep, 0);          // weights ready

    // SP-GEMM must wait for prep_weights (g_WspH)
    cudaStreamWaitEvent(g_s1, g_evPrep, 0);
    gemm_f16<<<dim3(MB, 8), 256, 0, g_s1>>>(X, 256, pWspH, pSP, 512, N);  // S|P
    cudaEventRecord(g_evS1, g_s1);

    gemm_f32s<<<dim3(MB, 4), 256>>>(ccw, 2048, pWkh, pWkl, pK, N);        // K
    u_tc<<<dim3(MB, 8), 256>>>(N);                                        // U

    // join: attn needs SP + cvt'd msgs + U
    cudaStreamWaitEvent(0, g_evS1, 0);
    cudaStreamWaitEvent(0, g_evS2, 0);
    attn_fused<<<(N + 3) / 4, 128>>>(ccwm, cwm, pidx, N);
    vproj_f16<<<dim3(MB, 8), 256>>>(N);
    gemm_h16<<<dim3(MB, 4), 256>>>(pV, pWfinH, out, N);                   // final
}

// round 16
// speedup vs baseline: 1.2000x; 1.2000x over previous
#include <cuda_runtime.h>
#include <cuda_bf16.h>
#include <cuda_fp16.h>
#include <cstdint>
#include <cstddef>

#define MAXN 30000
typedef unsigned long long u64;

__device__ float g_K[(size_t)MAXN * 256];
__device__ float g_SP[(size_t)MAXN * 512];
__device__ __half g_V[(size_t)MAXN * 256];
__device__ __half g_U[(size_t)MAXN * 8 * 256];
__device__ __half g_A[(size_t)MAXN * 8 * 256];
__device__ __nv_bfloat16 g_Wkh[256 * 256], g_Wkl[256 * 256];
__device__ __nv_bfloat16 g_WqTh[256 * 256], g_WqTl[256 * 256];
__device__ __half g_WspH[512 * 256];
__device__ __half g_WfinH[256 * 256];
__device__ __half g_WvH[256 * 256];
__device__ int g_maskMode;

// streams + events, created once at load time (host objects only)
static cudaStream_t g_s1;
static cudaEvent_t g_evPrep, g_evS1;
namespace {
struct StreamInit {
    StreamInit() {
        cudaStreamCreateWithFlags(&g_s1, cudaStreamNonBlocking);
        cudaEventCreateWithFlags(&g_evPrep, cudaEventDisableTiming);
        cudaEventCreateWithFlags(&g_evS1, cudaEventDisableTiming);
    }
};
StreamInit g_streamInit;
}

// packed fp32x2 ops (Blackwell; full fp32 precision, 2x issue rate)
#define PACK2(o, lo, hi) asm("mov.b64 %0, {%1,%2};" : "=l"(o) : "f"(lo), "f"(hi))
#define UNPACK2(lo, hi, v) asm("mov.b64 {%0,%1}, %2;" : "=f"(lo), "=f"(hi) : "l"(v))
#define FMA2(d, a, b, c) asm("fma.rn.f32x2 %0, %1, %2, %3;" : "=l"(d) : "l"(a), "l"(b), "l"(c))
#define MUL2(d, a, b) asm("mul.rn.f32x2 %0, %1, %2;" : "=l"(d) : "l"(a), "l"(b))

// ---------------- mask dtype detection (deterministic) ----------------
__global__ void detect_kernel(const unsigned char* __restrict__ m, int nelem) {
    __shared__ int s_nzoff, s_badf, s_anyf;
    if (threadIdx.x == 0) { s_nzoff = 0; s_badf = 0; s_anyf = 0; }
    __syncthreads();
    int words = min(nelem / 4, 1024);
    const unsigned int* wm = (const unsigned int*)m;
    int nz = 0, bf = 0, af = 0;
    for (int i = threadIdx.x; i < words; i += blockDim.x) {
        unsigned int w = wm[i];
        if (w >> 8) nz = 1;
        if (w != 0u && w != 0x3F800000u) bf = 1;
        if (w == 0x3F800000u) af = 1;
    }
    if (nz) atomicOr(&s_nzoff, 1);
    if (bf) atomicOr(&s_badf, 1);
    if (af) atomicOr(&s_anyf, 1);
    __syncthreads();
    if (threadIdx.x == 0)
        g_maskMode = (!s_badf && s_anyf) ? 2 : (!s_nzoff ? 1 : 0);
}

__device__ __forceinline__ bool mask_at(const void* p, int i, int mode) {
    if (mode == 0) return ((const unsigned char*)p)[i] != 0;
    if (mode == 1) return ((const int*)p)[i] != 0;
    return ((const float*)p)[i] != 0.0f;
}

// ---------------- weight prep: one kernel, 6 jobs ----------------
__global__ void prep_weights(const float* __restrict__ Wself, const float* __restrict__ Wpar,
                             const float* __restrict__ Wfin, const float* __restrict__ Wv,
                             const float* __restrict__ Wk, const float* __restrict__ Wq) {
    int r = blockIdx.x * 4 + (threadIdx.x >> 8);
    int c = threadIdx.x & 255;
    int job = blockIdx.y;
    size_t idx = (size_t)r * 256 + c;
    switch (job) {
        case 0: g_WspH[idx] = __float2half_rn(Wself[idx]); break;
        case 1: g_WspH[idx + 256 * 256] = __float2half_rn(Wpar[idx]); break;
        case 2: g_WfinH[idx] = __float2half_rn(Wfin[idx]); break;
        case 3: g_WvH[idx] = __float2half_rn(Wv[idx]); break;
        case 4: {
            float x = Wk[idx];
            __nv_bfloat16 h = __float2bfloat16(x);
            g_Wkh[idx] = h;
            g_Wkl[idx] = __float2bfloat16(x - __bfloat162float(h));
            break;
        }
        case 5: {
            float x = Wq[(size_t)c * 256 + r];  // transpose
            __nv_bfloat16 h = __float2bfloat16(x);
            g_WqTh[idx] = h;
            g_WqTl[idx] = __float2bfloat16(x - __bfloat162float(h));
            break;
        }
    }
}

// ---------------- helpers ----------------
__device__ __forceinline__ void split8(float4 a, float4 b, uint4& h, uint4& l) {
    float x[8] = {a.x, a.y, a.z, a.w, b.x, b.y, b.z, b.w};
    uint32_t hw[4], lw[4];
#pragma unroll
    for (int p = 0; p < 4; p++) {
        __nv_bfloat16 h0 = __float2bfloat16(x[2 * p]);
        __nv_bfloat16 h1 = __float2bfloat16(x[2 * p + 1]);
        __nv_bfloat16 l0 = __float2bfloat16(x[2 * p] - __bfloat162float(h0));
        __nv_bfloat16 l1 = __float2bfloat16(x[2 * p + 1] - __bfloat162float(h1));
        hw[p] = ((uint32_t)__bfloat16_as_ushort(h1) << 16) | __bfloat16_as_ushort(h0);
        lw[p] = ((uint32_t)__bfloat16_as_ushort(l1) << 16) | __bfloat16_as_ushort(l0);
    }
    h = make_uint4(hw[0], hw[1], hw[2], hw[3]);
    l = make_uint4(lw[0], lw[1], lw[2], lw[3]);
}

__device__ __forceinline__ uint4 cvt8_f16(float4 a, float4 b) {
    uint32_t w[4];
    w[0] = ((uint32_t)__half_as_ushort(__float2half_rn(a.y)) << 16) | __half_as_ushort(__float2half_rn(a.x));
    w[1] = ((uint32_t)__half_as_ushort(__float2half_rn(a.w)) << 16) | __half_as_ushort(__float2half_rn(a.z));
    w[2] = ((uint32_t)__half_as_ushort(__float2half_rn(b.y)) << 16) | __half_as_ushort(__float2half_rn(b.x));
    w[3] = ((uint32_t)__half_as_ushort(__float2half_rn(b.w)) << 16) | __half_as_ushort(__float2half_rn(b.z));
    return make_uint4(w[0], w[1], w[2], w[3]);
}

#define MMA_BF16(d, a, b) asm volatile( \
    "mma.sync.aligned.m16n8k16.row.col.f32.bf16.bf16.f32 " \
    "{%0,%1,%2,%3}, {%4,%5,%6,%7}, {%8,%9}, {%0,%1,%2,%3};\n" \
    : "+f"(d[0]), "+f"(d[1]), "+f"(d[2]), "+f"(d[3]) \
    : "r"(a[0]), "r"(a[1]), "r"(a[2]), "r"(a[3]), "r"(b[0]), "r"(b[1]))

#define MMA_F16(d, a, b) asm volatile( \
    "mma.sync.aligned.m16n8k16.row.col.f32.f16.f16.f32 " \
    "{%0,%1,%2,%3}, {%4,%5,%6,%7}, {%8,%9}, {%0,%1,%2,%3};\n" \
    : "+f"(d[0]), "+f"(d[1]), "+f"(d[2]), "+f"(d[3]) \
    : "r"(a[0]), "r"(a[1]), "r"(a[2]), "r"(a[3]), "r"(b[0]), "r"(b[1]))

// ---------------- 3-split bf16 GEMM (score path) ----------------
__global__ __launch_bounds__(256) void gemm_f32s(
    const float* __restrict__ A, long lda,
    const __nv_bfloat16* __restrict__ Bh, const __nv_bfloat16* __restrict__ Bl,
    float* __restrict__ C, int M) {
    __shared__ __nv_bfloat16 sAh[128][40], sAl[128][40];
    __shared__ __nv_bfloat16 sBh[64][40], sBl[64][40];
    const int t = threadIdx.x, lane = t & 31, w = t >> 5;
    const int m0 = blockIdx.x * 128, n0 = blockIdx.y * 64;
    const int wr = (w & 3) * 32, wc = (w >> 2) * 32;
    float acc[2][4][4];
#pragma unroll
    for (int i = 0; i < 2; i++)
#pragma unroll
        for (int j = 0; j < 4; j++)
#pragma unroll
            for (int q = 0; q < 4; q++) acc[i][j][q] = 0.f;

    const int ar = t >> 1, ao = (t & 1) * 16;
    const int br = t >> 2, bo = (t & 3) * 8;
    const int am = m0 + ar;
    const bool aok = (am < M);
    const float* pA = A + (size_t)(aok ? am : 0) * lda + ao;
    const __nv_bfloat16* pBh = Bh + (size_t)(n0 + br) * 256 + bo;
    const __nv_bfloat16* pBl = Bl + (size_t)(n0 + br) * 256 + bo;

    for (int k0 = 0; k0 < 256; k0 += 32) {
        float4 z = make_float4(0, 0, 0, 0);
        float4 a0 = aok ? *(const float4*)(pA + k0)      : z;
        float4 a1 = aok ? *(const float4*)(pA + k0 + 4)  : z;
        float4 a2 = aok ? *(const float4*)(pA + k0 + 8)  : z;
        float4 a3 = aok ? *(const float4*)(pA + k0 + 12) : z;
        uint4 h0, l0, h1, l1;
        split8(a0, a1, h0, l0);
        split8(a2, a3, h1, l1);
        *(uint4*)&sAh[ar][ao]     = h0;
        *(uint4*)&sAh[ar][ao + 8] = h1;
        *(uint4*)&sAl[ar][ao]     = l0;
        *(uint4*)&sAl[ar][ao + 8] = l1;
        *(uint4*)&sBh[br][bo] = *(const uint4*)(pBh + k0);
        *(uint4*)&sBl[br][bo] = *(const uint4*)(pBl + k0);
        __syncthreads();
#pragma unroll
        for (int kk = 0; kk < 32; kk += 16) {
            uint32_t afh[2][4], afl[2][4], bfh[4][2], bfl[4][2];
            const int arow = wr + (lane >> 2);
            const int acol = kk + (lane & 3) * 2;
#pragma unroll
            for (int mt = 0; mt < 2; mt++) {
                const int r0 = arow + mt * 16;
                afh[mt][0] = *(const uint32_t*)&sAh[r0][acol];
                afh[mt][1] = *(const uint32_t*)&sAh[r0 + 8][acol];
                afh[mt][2] = *(const uint32_t*)&sAh[r0][acol + 8];
                afh[mt][3] = *(const uint32_t*)&sAh[r0 + 8][acol + 8];
                afl[mt][0] = *(const uint32_t*)&sAl[r0][acol];
                afl[mt][1] = *(const uint32_t*)&sAl[r0 + 8][acol];
                afl[mt][2] = *(const uint32_t*)&sAl[r0][acol + 8];
                afl[mt][3] = *(const uint32_t*)&sAl[r0 + 8][acol + 8];
            }
#pragma unroll
            for (int nt = 0; nt < 4; nt++) {
                const int nr = wc + nt * 8 + (lane >> 2);
                bfh[nt][0] = *(const uint32_t*)&sBh[nr][acol];
                bfh[nt][1] = *(const uint32_t*)&sBh[nr][acol + 8];
                bfl[nt][0] = *(const uint32_t*)&sBl[nr][acol];
                bfl[nt][1] = *(const uint32_t*)&sBl[nr][acol + 8];
            }
#pragma unroll
            for (int mt = 0; mt < 2; mt++)
#pragma unroll
                for (int nt = 0; nt < 4; nt++) {
                    MMA_BF16(acc[mt][nt], afh[mt], bfh[nt]);
                    MMA_BF16(acc[mt][nt], afh[mt], bfl[nt]);
                    MMA_BF16(acc[mt][nt], afl[mt], bfh[nt]);
                }
        }
        __syncthreads();
    }
    const int grp = lane >> 2, qc = (lane & 3) * 2;
#pragma unroll
    for (int mt = 0; mt < 2; mt++)
#pragma unroll
        for (int nt = 0; nt < 4; nt++) {
            const int rg = m0 + wr + mt * 16 + grp;
            const int cg = n0 + wc + nt * 8 + qc;
            if (rg < M)
                *(float2*)&C[(size_t)rg * 256 + cg] =
                    make_float2(acc[mt][nt][0], acc[mt][nt][1]);
            if (rg + 8 < M)
                *(float2*)&C[(size_t)(rg + 8) * 256 + cg] =
                    make_float2(acc[mt][nt][2], acc[mt][nt][3]);
        }
}

// ---------------- fp16 GEMM, A fp32 in gmem ----------------
__global__ __launch_bounds__(256) void gemm_f16(
    const float* __restrict__ A, long lda,
    const __half* __restrict__ B,
    float* __restrict__ C, long ldc, int M) {
    __shared__ __half sA[128][40];
    __shared__ __half sB[64][40];
    const int t = threadIdx.x, lane = t & 31, w = t >> 5;
    const int m0 = blockIdx.x * 128, n0 = blockIdx.y * 64;
    const int wr = (w & 3) * 32, wc = (w >> 2) * 32;
    float acc[2][4][4];
#pragma unroll
    for (int i = 0; i < 2; i++)
#pragma unroll
        for (int j = 0; j < 4; j++)
#pragma unroll
            for (int q = 0; q < 4; q++) acc[i][j][q] = 0.f;

    const int ar = t >> 1, ao = (t & 1) * 16;
    const int br = t >> 2, bo = (t & 3) * 8;
    const int am = m0 + ar;
    const bool aok = (am < M);
    const float* pA = A + (size_t)(aok ? am : 0) * lda + ao;
    const __half* pB = B + (size_t)(n0 + br) * 256 + bo;

    const float4 z = make_float4(0, 0, 0, 0);
    float4 a0 = aok ? *(const float4*)(pA)      : z;
    float4 a1 = aok ? *(const float4*)(pA + 4)  : z;
    float4 a2 = aok ? *(const float4*)(pA + 8)  : z;
    float4 a3 = aok ? *(const float4*)(pA + 12) : z;
    uint4 rb = *(const uint4*)(pB);

    for (int k0 = 0; k0 < 256; k0 += 32) {
        *(uint4*)&sA[ar][ao]     = cvt8_f16(a0, a1);
        *(uint4*)&sA[ar][ao + 8] = cvt8_f16(a2, a3);
        *(uint4*)&sB[br][bo] = rb;
        __syncthreads();
        if (k0 + 32 < 256) {
            const int kn = k0 + 32;
            a0 = aok ? *(const float4*)(pA + kn)      : z;
            a1 = aok ? *(const float4*)(pA + kn + 4)  : z;
            a2 = aok ? *(const float4*)(pA + kn + 8)  : z;
            a3 = aok ? *(const float4*)(pA + kn + 12) : z;
            rb = *(const uint4*)(pB + kn);
        }
#pragma unroll
        for (int kk = 0; kk < 32; kk += 16) {
            uint32_t af[2][4], bf[4][2];
            const int arow = wr + (lane >> 2);
            const int acol = kk + (lane & 3) * 2;
#pragma unroll
            for (int mt = 0; mt < 2; mt++) {
                const int r0 = arow + mt * 16;
                af[mt][0] = *(const uint32_t*)&sA[r0][acol];
                af[mt][1] = *(const uint32_t*)&sA[r0 + 8][acol];
                af[mt][2] = *(const uint32_t*)&sA[r0][acol + 8];
                af[mt][3] = *(const uint32_t*)&sA[r0 + 8][acol + 8];
            }
#pragma unroll
            for (int nt = 0; nt < 4; nt++) {
                const int nr = wc + nt * 8 + (lane >> 2);
                bf[nt][0] = *(const uint32_t*)&sB[nr][acol];
                bf[nt][1] = *(const uint32_t*)&sB[nr][acol + 8];
            }
#pragma unroll
            for (int mt = 0; mt < 2; mt++)
#pragma unroll
                for (int nt = 0; nt < 4; nt++)
                    MMA_F16(acc[mt][nt], af[mt], bf[nt]);
        }
        __syncthreads();
    }
    const int grp = lane >> 2, qc = (lane & 3) * 2;
#pragma unroll
    for (int mt = 0; mt < 2; mt++)
#pragma unroll
        for (int nt = 0; nt < 4; nt++) {
            const int rg = m0 + wr + mt * 16 + grp;
            const int cg = n0 + wc + nt * 8 + qc;
            if (rg < M)
                *(float2*)&C[(size_t)rg * ldc + cg] =
                    make_float2(acc[mt][nt][0], acc[mt][nt][1]);
            if (rg + 8 < M)
                *(float2*)&C[(size_t)(rg + 8) * ldc + cg] =
                    make_float2(acc[mt][nt][2], acc[mt][nt][3]);
        }
}

// ---------------- fp16 GEMM, A fp16 in gmem (final proj) -------------------
__global__ __launch_bounds__(256) void gemm_h16(
    const __half* __restrict__ A,
    const __half* __restrict__ B,
    float* __restrict__ C, int M) {
    __shared__ __half sA[128][40];
    __shared__ __half sB[64][40];
    const int t = threadIdx.x, lane = t & 31, w = t >> 5;
    const int m0 = blockIdx.x * 128, n0 = blockIdx.y * 64;
    const int wr = (w & 3) * 32, wc = (w >> 2) * 32;
    float acc[2][4][4];
#pragma unroll
    for (int i = 0; i < 2; i++)
#pragma unroll
        for (int j = 0; j < 4; j++)
#pragma unroll
            for (int q = 0; q < 4; q++) acc[i][j][q] = 0.f;

    const int ar = t >> 1, ao = (t & 1) * 16;
    const int br = t >> 2, bo = (t & 3) * 8;
    const int am = m0 + ar;
    const bool aok = (am < M);
    const __half* pA = A + (size_t)(aok ? am : 0) * 256 + ao;
    const __half* pB = B + (size_t)(n0 + br) * 256 + bo;

    const uint4 uz = make_uint4(0, 0, 0, 0);
    uint4 ra0 = aok ? *(const uint4*)(pA)     : uz;
    uint4 ra1 = aok ? *(const uint4*)(pA + 8) : uz;
    uint4 rb  = *(const uint4*)(pB);

    for (int k0 = 0; k0 < 256; k0 += 32) {
        *(uint4*)&sA[ar][ao]     = ra0;
        *(uint4*)&sA[ar][ao + 8] = ra1;
        *(uint4*)&sB[br][bo] = rb;
        __syncthreads();
        if (k0 + 32 < 256) {
            const int kn = k0 + 32;
            ra0 = aok ? *(const uint4*)(pA + kn)     : uz;
            ra1 = aok ? *(const uint4*)(pA + kn + 8) : uz;
            rb  = *(const uint4*)(pB + kn);
        }
#pragma unroll
        for (int kk = 0; kk < 32; kk += 16) {
            uint32_t af[2][4], bf[4][2];
            const int arow = wr + (lane >> 2);
            const int acol = kk + (lane & 3) * 2;
#pragma unroll
            for (int mt = 0; mt < 2; mt++) {
                const int r0 = arow + mt * 16;
                af[mt][0] = *(const uint32_t*)&sA[r0][acol];
                af[mt][1] = *(const uint32_t*)&sA[r0 + 8][acol];
                af[mt][2] = *(const uint32_t*)&sA[r0][acol + 8];
                af[mt][3] = *(const uint32_t*)&sA[r0 + 8][acol + 8];
            }
#pragma unroll
            for (int nt = 0; nt < 4; nt++) {
                const int nr = wc + nt * 8 + (lane >> 2);
                bf[nt][0] = *(const uint32_t*)&sB[nr][acol];
                bf[nt][1] = *(const uint32_t*)&sB[nr][acol + 8];
            }
#pragma unroll
            for (int mt = 0; mt < 2; mt++)
#pragma unroll
                for (int nt = 0; nt < 4; nt++)
                    MMA_F16(acc[mt][nt], af[mt], bf[nt]);
        }
        __syncthreads();
    }
    const int grp = lane >> 2, qc = (lane & 3) * 2;
#pragma unroll
    for (int mt = 0; mt < 2; mt++)
#pragma unroll
        for (int nt = 0; nt < 4; nt++) {
            const int rg = m0 + wr + mt * 16 + grp;
            const int cg = n0 + wc + nt * 8 + qc;
            if (rg < M)
                *(float2*)&C[(size_t)rg * 256 + cg] =
                    make_float2(acc[mt][nt][0], acc[mt][nt][1]);
            if (rg + 8 < M)
                *(float2*)&C[(size_t)(rg + 8) * 256 + cg] =
                    make_float2(acc[mt][nt][2], acc[mt][nt][3]);
        }
}

// ---------------- u via tensor cores: A staged once, i0 loop inside ---------
__global__ __launch_bounds__(256) void u_tc(int M) {
    __shared__ __nv_bfloat16 sAh[128][40], sAl[128][40];
    __shared__ __nv_bfloat16 sBh[64][40], sBl[64][40];
    const int t = threadIdx.x, lane = t & 31, w = t >> 5;
    const int m0 = blockIdx.x * 128, h = blockIdx.y;
    const int wr = (w & 3) * 32, wc = (w >> 2) * 32;
    const int ar = t >> 1, ao = (t & 1) * 16;
    const int br = t >> 2, bo = (t & 3) * 8;
    const int am = m0 + ar;
    const bool aok = (am < M);
    const int grp = lane >> 2, qc = (lane & 3) * 2;

    {
        float4 z = make_float4(0, 0, 0, 0);
        const float* pA = g_K + (size_t)(aok ? am : 0) * 256 + h * 32 + ao;
        float4 a0 = aok ? *(const float4*)(pA)      : z;
        float4 a1 = aok ? *(const float4*)(pA + 4)  : z;
        float4 a2 = aok ? *(const float4*)(pA + 8)  : z;
        float4 a3 = aok ? *(const float4*)(pA + 12) : z;
        uint4 h0, l0, h1, l1;
        split8(a0, a1, h0, l0);
        split8(a2, a3, h1, l1);
        *(uint4*)&sAh[ar][ao]     = h0;
        *(uint4*)&sAh[ar][ao + 8] = h1;
        *(uint4*)&sAl[ar][ao]     = l0;
        *(uint4*)&sAl[ar][ao + 8] = l1;
    }

    for (int i0 = 0; i0 < 256; i0 += 64) {
        __syncthreads();
        *(uint4*)&sBh[br][bo] = *(const uint4*)&g_WqTh[(size_t)(i0 + br) * 256 + h * 32 + bo];
        *(uint4*)&sBl[br][bo] = *(const uint4*)&g_WqTl[(size_t)(i0 + br) * 256 + h * 32 + bo];
        __syncthreads();

        float acc[2][4][4];
#pragma unroll
        for (int i = 0; i < 2; i++)
#pragma unroll
            for (int j = 0; j < 4; j++)
#pragma unroll
                for (int q = 0; q < 4; q++) acc[i][j][q] = 0.f;

#pragma unroll
        for (int kk = 0; kk < 32; kk += 16) {
            uint32_t afh[2][4], afl[2][4], bfh[4][2], bfl[4][2];
            const int arow = wr + (lane >> 2);
            const int acol = kk + (lane & 3) * 2;
#pragma unroll
            for (int mt = 0; mt < 2; mt++) {
                const int r0 = arow + mt * 16;
                afh[mt][0] = *(const uint32_t*)&sAh[r0][acol];
                afh[mt][1] = *(const uint32_t*)&sAh[r0 + 8][acol];
                afh[mt][2] = *(const uint32_t*)&sAh[r0][acol + 8];
                afh[mt][3] = *(const uint32_t*)&sAh[r0 + 8][acol + 8];
                afl[mt][0] = *(const uint32_t*)&sAl[r0][acol];
                afl[mt][1] = *(const uint32_t*)&sAl[r0 + 8][acol];
                afl[mt][2] = *(const uint32_t*)&sAl[r0][acol + 8];
                afl[mt][3] = *(const uint32_t*)&sAl[r0 + 8][acol + 8];
            }
#pragma unroll
            for (int nt = 0; nt < 4; nt++) {
                const int nr = wc + nt * 8 + (lane >> 2);
                bfh[nt][0] = *(const uint32_t*)&sBh[nr][acol];
                bfh[nt][1] = *(const uint32_t*)&sBh[nr][acol + 8];
                bfl[nt][0] = *(const uint32_t*)&sBl[nr][acol];
                bfl[nt][1] = *(const uint32_t*)&sBl[nr][acol + 8];
            }
#pragma unroll
            for (int mt = 0; mt < 2; mt++)
#pragma unroll
                for (int nt = 0; nt < 4; nt++) {
                    MMA_BF16(acc[mt][nt], afh[mt], bfh[nt]);
                    MMA_BF16(acc[mt][nt], afh[mt], bfl[nt]);
                    MMA_BF16(acc[mt][nt], afl[mt], bfh[nt]);
                }
        }

#pragma unroll
        for (int mt = 0; mt < 2; mt++)
#pragma unroll
            for (int nt = 0; nt < 4; nt++) {
                const int rg = m0 + wr + mt * 16 + grp;
                const int cg = h * 256 + i0 + wc + nt * 8 + qc;
                if (rg < M) {
                    __half2 v = __floats2half2_rn(acc[mt][nt][0], acc[mt][nt][1]);
                    *(__half2*)&g_U[(size_t)rg * 2048 + cg] = v;
                }
                if (rg + 8 < M) {
                    __half2 v = __floats2half2_rn(acc[mt][nt][2], acc[mt][nt][3]);
                    *(__half2*)&g_U[(size_t)(rg + 8) * 2048 + cg] = v;
                }
            }
    }
}

// ---------------- vproj: A fp16 in gmem, fp16 Wv, fp16 V out ---------------
__global__ __launch_bounds__(256) void vproj_f16(int M) {
    __shared__ __half sA[128][40];
    __shared__ __half sB[32][40];
    const int t = threadIdx.x, lane = t & 31, w = t >> 5;
    const int m0 = blockIdx.x * 128, h = blockIdx.y;
    const int wr = (w & 3) * 32, wc = (w >> 2) * 16;
    float acc[2][2][4];
#pragma unroll
    for (int i = 0; i < 2; i++)
#pragma unroll
        for (int j = 0; j < 2; j++)
#pragma unroll
            for (int q = 0; q < 4; q++) acc[i][j][q] = 0.f;

    const int ar = t >> 1, ao = (t & 1) * 16;
    const int br = t >> 3, bo = (t & 7) * 4;
    const int am = m0 + ar;
    const bool aok = (am < M);
    const __half* pA = g_A + (size_t)(aok ? am : 0) * 2048 + h * 256 + ao;
    const __half* pB = g_WvH + (size_t)(h * 32 + br) * 256 + bo;

    const uint4 uz = make_uint4(0, 0, 0, 0);
    uint4 ra0 = aok ? *(const uint4*)(pA)     : uz;
    uint4 ra1 = aok ? *(const uint4*)(pA + 8) : uz;
    uint2 rb  = *(const uint2*)(pB);

    for (int k0 = 0; k0 < 256; k0 += 32) {
        *(uint4*)&sA[ar][ao]     = ra0;
        *(uint4*)&sA[ar][ao + 8] = ra1;
        *(uint2*)&sB[br][bo] = rb;
        __syncthreads();
        if (k0 + 32 < 256) {
            const int kn = k0 + 32;
            ra0 = aok ? *(const uint4*)(pA + kn)     : uz;
            ra1 = aok ? *(const uint4*)(pA + kn + 8) : uz;
            rb  = *(const uint2*)(pB + kn);
        }
#pragma unroll
        for (int kk = 0; kk < 32; kk += 16) {
            uint32_t af[2][4], bf[2][2];
            const int arow = wr + (lane >> 2);
            const int acol = kk + (lane & 3) * 2;
#pragma unroll
            for (int mt = 0; mt < 2; mt++) {
                const int r0 = arow + mt * 16;
                af[mt][0] = *(const uint32_t*)&sA[r0][acol];
                af[mt][1] = *(const uint32_t*)&sA[r0 + 8][acol];
                af[mt][2] = *(const uint32_t*)&sA[r0][acol + 8];
                af[mt][3] = *(const uint32_t*)&sA[r0 + 8][acol + 8];
            }
#pragma unroll
            for (int nt = 0; nt < 2; nt++) {
                const int nr = wc + nt * 8 + (lane >> 2);
                bf[nt][0] = *(const uint32_t*)&sB[nr][acol];
                bf[nt][1] = *(const uint32_t*)&sB[nr][acol + 8];
            }
#pragma unroll
            for (int mt = 0; mt < 2; mt++)
#pragma unroll
                for (int nt = 0; nt < 2; nt++)
                    MMA_F16(acc[mt][nt], af[mt], bf[nt]);
        }
        __syncthreads();
    }
    const int grp = lane >> 2, qc = (lane & 3) * 2;
#pragma unroll
    for (int mt = 0; mt < 2; mt++)
#pragma unroll
        for (int nt = 0; nt < 2; nt++) {
            const int rg = m0 + wr + mt * 16 + grp;
            const int cg = h * 32 + wc + nt * 8 + qc;
            if (rg < M) {
                __half2 v = __floats2half2_rn(acc[mt][nt][0], acc[mt][nt][1]);
                *(__half2*)&g_V[(size_t)rg * 256 + cg] = v;
            }
            if (rg + 8 < M) {
                __half2 v = __floats2half2_rn(acc[mt][nt][2], acc[mt][nt][3]);
                *(__half2*)&g_V[(size_t)(rg + 8) * 256 + cg] = v;
            }
        }
}

// ---------------- attention: warp-per-node, vectorized d = lane*8+j ---------
// lane owns 8 contiguous d; msg = 2x LDG.128, u row = 1x LDG.128 (fp16),
// A write = 1x STG.128 per head. Score fold unchanged (sum over all d).
__global__ __launch_bounds__(128) void attn_fused(
        const float* __restrict__ ccw, const float* __restrict__ cw,
        const void* __restrict__ ccwm, const void* __restrict__ cwm,
        const int* __restrict__ pidx, int N) {
    __shared__ float p_sm[4][8][20];
    const int t = threadIdx.x, lane = t & 31, w = t >> 5;
    const int n = blockIdx.x * 4 + w;
    if (n >= N) return;
    const size_t nb = n;
    const int mode = g_maskMode;
    const int myh = (((lane >> 4) & 1) << 2) | (((lane >> 3) & 1) << 1) | ((lane >> 2) & 1);
    const float NEG = __int_as_float(0xff800000);
    const float SCALE = 0.17677669529663688f;
    const size_t ppar = (size_t)pidx[n] * 512 + 256;
    const int d0 = lane * 8;

    // u: 1 uint4 (8 fp16) per head
    u64 up[8][4];
#pragma unroll
    for (int h = 0; h < 8; h++) {
        uint4 uv = *(const uint4*)&g_U[nb * 2048 + h * 256 + d0];
        uint32_t wv[4] = {uv.x, uv.y, uv.z, uv.w};
#pragma unroll
        for (int j = 0; j < 4; j++) {
            float2 f = __half22float2(*(__half2*)&wv[j]);
            PACK2(up[h][j], f.x, f.y);
        }
    }

    float sc[18];
#pragma unroll
    for (int s = 0; s < 18; s++) {
        const float* src;
        if (s < 8)       src = ccw + nb * 2048 + (size_t)s * 256;
        else if (s == 8) src = g_SP + nb * 512;
        else if (s == 9) src = g_SP + ppar;
        else             src = cw + nb * 2048 + (size_t)(s - 10) * 256;
        float4 a = *(const float4*)&src[d0];
        float4 b = *(const float4*)&src[d0 + 4];
        u64 mp[4];
        PACK2(mp[0], a.x, a.y);
        PACK2(mp[1], a.z, a.w);
        PACK2(mp[2], b.x, b.y);
        PACK2(mp[3], b.z, b.w);
        float part[8];
#pragma unroll
        for (int h = 0; h < 8; h++) {
            u64 ac;
            MUL2(ac, mp[0], up[h][0]);
            FMA2(ac, mp[1], up[h][1], ac);
            FMA2(ac, mp[2], up[h][2], ac);
            FMA2(ac, mp[3], up[h][3], ac);
            float lo, hi;
            UNPACK2(lo, hi, ac);
            part[h] = lo + hi;
        }
#pragma unroll
        for (int i = 0; i < 4; i++) {
            float a2 = part[i], b2 = part[i + 4];
            float send = (lane & 16) ? a2 : b2;
            float recv = __shfl_xor_sync(0xFFFFFFFFu, send, 16);
            part[i] = ((lane & 16) ? b2 : a2) + recv;
        }
#pragma unroll
        for (int i = 0; i < 2; i++) {
            float a2 = part[i], b2 = part[i + 2];
            float send = (lane & 8) ? a2 : b2;
            float recv = __shfl_xor_sync(0xFFFFFFFFu, send, 8);
            part[i] = ((lane & 8) ? b2 : a2) + recv;
        }
        {
            float a2 = part[0], b2 = part[1];
            float send = (lane & 4) ? a2 : b2;
            float recv = __shfl_xor_sync(0xFFFFFFFFu, send, 4);
            part[0] = ((lane & 4) ? b2 : a2) + recv;
        }
        part[0] += __shfl_xor_sync(0xFFFFFFFFu, part[0], 2);
        part[0] += __shfl_xor_sync(0xFFFFFFFFu, part[0], 1);
        sc[s] = part[0];
    }

    unsigned vb = 3u << 8;
#pragma unroll
    for (int s = 0; s < 8; s++)
        if (mask_at(ccwm, n * 8 + s, mode)) vb |= 1u << s;
#pragma unroll
    for (int s = 0; s < 8; s++)
        if (mask_at(cwm, n * 8 + s, mode)) vb |= 1u << (10 + s);
    float mx = NEG;
#pragma unroll
    for (int s = 0; s < 18; s++)
        if ((vb >> s) & 1) mx = fmaxf(mx, sc[s] * SCALE);
    float sum = 0.f;
    float pr[18];
#pragma unroll
    for (int s = 0; s < 18; s++) {
        float e = ((vb >> s) & 1) ? __expf(sc[s] * SCALE - mx) : 0.f;
        pr[s] = e;
        sum += e;
    }
    const float inv = 1.f / sum;
    if ((lane & 3) == 0) {
#pragma unroll
        for (int s = 0; s < 18; s++) p_sm[w][myh][s] = pr[s] * inv;
    }
    __syncwarp();

    u64 acc2[8][4];
#pragma unroll
    for (int h = 0; h < 8; h++)
#pragma unroll
        for (int j = 0; j < 4; j++) acc2[h][j] = 0ULL;
#pragma unroll
    for (int s = 0; s < 18; s++) {
        const float* src;
        if (s < 8)       src = ccw + nb * 2048 + (size_t)s * 256;
        else if (s == 8) src = g_SP + nb * 512;
        else if (s == 9) src = g_SP + ppar;
        else             src = cw + nb * 2048 + (size_t)(s - 10) * 256;
        float4 a = *(const float4*)&src[d0];
        float4 b = *(const float4*)&src[d0 + 4];
        u64 mp[4];
        PACK2(mp[0], a.x, a.y);
        PACK2(mp[1], a.z, a.w);
        PACK2(mp[2], b.x, b.y);
        PACK2(mp[3], b.z, b.w);
#pragma unroll
        for (int h = 0; h < 8; h++) {
            float ph = p_sm[w][h][s];
            u64 pp;
            PACK2(pp, ph, ph);
#pragma unroll
            for (int j = 0; j < 4; j++)
                FMA2(acc2[h][j], pp, mp[j], acc2[h][j]);
        }
    }
#pragma unroll
    for (int h = 0; h < 8; h++) {
        uint32_t wv[4];
#pragma unroll
        for (int j = 0; j < 4; j++) {
            float lo, hi;
            UNPACK2(lo, hi, acc2[h][j]);
            __half2 h2 = __floats2half2_rn(lo, hi);
            wv[j] = *(uint32_t*)&h2;
        }
        *(uint4*)&g_A[nb * 2048 + h * 256 + d0] = make_uint4(wv[0], wv[1], wv[2], wv[3]);
    }
}

extern "C" void kernel_launch(void* const* d_in, const int* in_sizes, int n_in,
                              void* d_out, int out_size) {
    const float* X    = (const float*)d_in[0];
    const int*   pidx = (const int*)d_in[1];
    const float* ccw  = (const float*)d_in[2];
    const void*  ccwm = d_in[3];
    const float* cw   = (const float*)d_in[4];
    const void*  cwm  = d_in[5];
    const float* Wself = (const float*)d_in[6];
    const float* Wpar  = (const float*)d_in[7];
    const float* Wq    = (const float*)d_in[8];
    const float* Wk    = (const float*)d_in[9];
    const float* Wv    = (const float*)d_in[10];
    const float* Wfin  = (const float*)d_in[11];
    float* out = (float*)d_out;
    const int N = in_sizes[0] / 256;

    float *pK, *pSP;
    __half *pV;
    __nv_bfloat16 *pWkh, *pWkl;
    __half *pWspH, *pWfinH;
    cudaGetSymbolAddress((void**)&pK, g_K);
    cudaGetSymbolAddress((void**)&pV, g_V);
    cudaGetSymbolAddress((void**)&pSP, g_SP);
    cudaGetSymbolAddress((void**)&pWkh, g_Wkh);
    cudaGetSymbolAddress((void**)&pWkl, g_Wkl);
    cudaGetSymbolAddress((void**)&pWspH, g_WspH);
    cudaGetSymbolAddress((void**)&pWfinH, g_WfinH);

    detect_kernel<<<1, 256>>>((const unsigned char*)ccwm, in_sizes[3]);
    prep_weights<<<dim3(64, 6), 1024>>>(Wself, Wpar, Wfin, Wv, Wk, Wq);
    cudaEventRecord(g_evPrep, 0);   // weights ready

    const int MB = (N + 127) / 128;

    // fork: SP-GEMM on side stream (after weights), K + U on main
    cudaStreamWaitEvent(g_s1, g_evPrep, 0);
    gemm_f16<<<dim3(MB, 8), 256, 0, g_s1>>>(X, 256, pWspH, pSP, 512, N);  // S|P
    cudaEventRecord(g_evS1, g_s1);

    gemm_f32s<<<dim3(MB, 4), 256>>>(ccw, 2048, pWkh, pWkl, pK, N);        // K
    u_tc<<<dim3(MB, 8), 256>>>(N);                                        // U

    // join: attn needs SP + U
    cudaStreamWaitEvent(0, g_evS1, 0);
    attn_fused<<<(N + 3) / 4, 128>>>(ccw, cw, ccwm, cwm, pidx, N);
    vproj_f16<<<dim3(MB, 8), 256>>>(N);
    gemm_h16<<<dim3(MB, 4), 256>>>(pV, pWfinH, out, N);                   // final
}